// round 2
// baseline (speedup 1.0000x reference)
#include <cuda_runtime.h>
#include <cstdint>

#define NEG_SLOPE 0.2f

static constexpr int Bb = 8;
static constexpr int Nn = 2048;
static constexpr int Dd = 128;

// Scratch (device globals; allocation-free rule)
__device__ float g_h[Bb * Nn * Dd];      // h, rounded to tf32 values stored as fp32
__device__ float g_ssrc[Bb * Nn];
__device__ float g_sdst[Bb * Nn];
__device__ float g_invd[Bb * Nn];

__device__ __forceinline__ uint32_t f2tf(float x) {
    uint32_t r;
    asm("cvt.rna.tf32.f32 %0, %1;" : "=r"(r) : "f"(x));
    return r;
}

__device__ __forceinline__ float lrelu(float v) { return v > 0.f ? v : NEG_SLOPE * v; }

__device__ __forceinline__ void mma8(float* d, const uint32_t* a, const uint32_t* b) {
    asm volatile(
        "mma.sync.aligned.m16n8k8.row.col.f32.tf32.tf32.f32 "
        "{%0,%1,%2,%3},{%4,%5,%6,%7},{%8,%9},{%0,%1,%2,%3};\n"
        : "+f"(d[0]), "+f"(d[1]), "+f"(d[2]), "+f"(d[3])
        : "r"(a[0]), "r"(a[1]), "r"(a[2]), "r"(a[3]), "r"(b[0]), "r"(b[1]));
}

__device__ __forceinline__ void cp16(void* s, const void* g) {
    uint32_t sa = (uint32_t)__cvta_generic_to_shared(s);
    asm volatile("cp.async.cg.shared.global [%0], [%1], 16;" :: "r"(sa), "l"(g));
}
__device__ __forceinline__ void cp_commit() { asm volatile("cp.async.commit_group;"); }
__device__ __forceinline__ void cp_wait0()  { asm volatile("cp.async.wait_group 0;"); }

// ---------------------------------------------------------------------------
// K1: h = x @ W  (M=16384, N=128, K=128), tf32 mma, store tf32-rounded h.
// Epilogue also computes s_src/s_dst per row (folded former k2_s).
// ---------------------------------------------------------------------------
__global__ __launch_bounds__(256) void k1_h(const float* __restrict__ x,
                                            const float* __restrict__ W,
                                            const float* __restrict__ a) {
    __shared__ float As[64][36];
    __shared__ float Bs[32][136];
    __shared__ float red[64][2];
    int tid = threadIdx.x;
    int lane = tid & 31, w = tid >> 5;
    int wm = w >> 2, wn = w & 3;
    int g = lane >> 2, tg = lane & 3;
    long i0 = (long)blockIdx.x * 64;

    // preload attention-vector pairs for this thread's columns
    float2 asv[4], adv[4];
#pragma unroll
    for (int nt = 0; nt < 4; nt++) {
        int c = wn * 32 + nt * 8 + 2 * tg;
        asv[nt].x = __ldg(a + c);       asv[nt].y = __ldg(a + c + 1);
        adv[nt].x = __ldg(a + 128 + c); adv[nt].y = __ldg(a + 128 + c + 1);
    }
    if (tid < 128) ((float*)red)[tid] = 0.f;

    float acc[2][4][4];
#pragma unroll
    for (int mt = 0; mt < 2; mt++)
#pragma unroll
        for (int nt = 0; nt < 4; nt++)
#pragma unroll
            for (int q = 0; q < 4; q++) acc[mt][nt][q] = 0.f;

#pragma unroll
    for (int kc = 0; kc < 4; kc++) {
        int k0 = kc * 32;
        __syncthreads();
#pragma unroll
        for (int t = 0; t < 2; t++) {
            int e = tid + t * 256;
            int r = e >> 3, c4 = (e & 7) * 4;
            float4 xv = *(const float4*)(x + (i0 + r) * 128 + k0 + c4);
            uint4 o;
            o.x = f2tf(xv.x); o.y = f2tf(xv.y); o.z = f2tf(xv.z); o.w = f2tf(xv.w);
            *(uint4*)&As[r][c4] = o;
        }
#pragma unroll
        for (int t = 0; t < 4; t++) {
            int f = tid + t * 256;
            int r = f >> 5, c4 = (f & 31) * 4;
            float4 wv = *(const float4*)(W + (k0 + r) * 128 + c4);
            uint4 o;
            o.x = f2tf(wv.x); o.y = f2tf(wv.y); o.z = f2tf(wv.z); o.w = f2tf(wv.w);
            *(uint4*)&Bs[r][c4] = o;
        }
        __syncthreads();
#pragma unroll
        for (int ks = 0; ks < 4; ks++) {
            int ka = ks * 8;
            uint32_t af[2][4], bf[4][2];
#pragma unroll
            for (int mt = 0; mt < 2; mt++) {
                int rA = wm * 32 + mt * 16 + g;
                af[mt][0] = __float_as_uint(As[rA][ka + tg]);
                af[mt][1] = __float_as_uint(As[rA + 8][ka + tg]);
                af[mt][2] = __float_as_uint(As[rA][ka + tg + 4]);
                af[mt][3] = __float_as_uint(As[rA + 8][ka + tg + 4]);
            }
#pragma unroll
            for (int nt = 0; nt < 4; nt++) {
                int cB = wn * 32 + nt * 8 + g;
                bf[nt][0] = __float_as_uint(Bs[ka + tg][cB]);
                bf[nt][1] = __float_as_uint(Bs[ka + tg + 4][cB]);
            }
#pragma unroll
            for (int mt = 0; mt < 2; mt++)
#pragma unroll
                for (int nt = 0; nt < 4; nt++) mma8(acc[mt][nt], af[mt], bf[nt]);
        }
    }

    // store h rounded to tf32 (so downstream mma operands are valid tf32)
#pragma unroll
    for (int mt = 0; mt < 2; mt++)
#pragma unroll
        for (int nt = 0; nt < 4; nt++) {
            long r = i0 + wm * 32 + mt * 16 + g;
            int c = wn * 32 + nt * 8 + 2 * tg;
            float2 v0, v1;
            v0.x = __uint_as_float(f2tf(acc[mt][nt][0]));
            v0.y = __uint_as_float(f2tf(acc[mt][nt][1]));
            v1.x = __uint_as_float(f2tf(acc[mt][nt][2]));
            v1.y = __uint_as_float(f2tf(acc[mt][nt][3]));
            *(float2*)(g_h + r * 128 + c) = v0;
            *(float2*)(g_h + (r + 8) * 128 + c) = v1;
        }

    // folded k2_s: s_src/s_dst via shfl + smem-atomic reduction
    __syncthreads();
#pragma unroll
    for (int mt = 0; mt < 2; mt++)
#pragma unroll
        for (int half = 0; half < 2; half++) {
            int rl = wm * 32 + mt * 16 + g + 8 * half;
            float s = 0.f, d = 0.f;
#pragma unroll
            for (int nt = 0; nt < 4; nt++) {
                float v0 = acc[mt][nt][2 * half];
                float v1 = acc[mt][nt][2 * half + 1];
                s += v0 * asv[nt].x + v1 * asv[nt].y;
                d += v0 * adv[nt].x + v1 * adv[nt].y;
            }
            s += __shfl_xor_sync(0xFFFFFFFFu, s, 1);
            s += __shfl_xor_sync(0xFFFFFFFFu, s, 2);
            d += __shfl_xor_sync(0xFFFFFFFFu, d, 1);
            d += __shfl_xor_sync(0xFFFFFFFFu, d, 2);
            if (tg == 0) {
                atomicAdd(&red[rl][0], s);
                atomicAdd(&red[rl][1], d);
            }
        }
    __syncthreads();
    if (tid < 64) {
        g_ssrc[i0 + tid] = red[tid][0];
        g_sdst[i0 + tid] = red[tid][1];
    }
}

// ---------------------------------------------------------------------------
// K2b: invd[i] = 1 / sum_j exp(lrelu(s_i + s_j))   (per batch)
// ---------------------------------------------------------------------------
__global__ __launch_bounds__(256) void k2_den() {
    __shared__ float sd[2048];
    __shared__ float part[256];
    int tid = threadIdx.x;
    int b = blockIdx.x >> 5, ic = blockIdx.x & 31;
    const float* sdg = g_sdst + b * 2048;
#pragma unroll
    for (int t = 0; t < 2; t++) {
        int f = tid + t * 256;
        *(float4*)&sd[f * 4] = *(const float4*)(sdg + f * 4);
    }
    int r = tid & 63, q = tid >> 6;
    float si = g_ssrc[b * 2048 + ic * 64 + r];
    __syncthreads();
    float acc = 0.f;
    int j0 = q * 512;
#pragma unroll 8
    for (int j = 0; j < 512; j++) {
        float e = si + sd[j0 + j];
        acc += __expf(lrelu(e));
    }
    part[tid] = acc;
    __syncthreads();
    if (tid < 64) {
        float den = part[tid] + part[tid + 64] + part[tid + 128] + part[tid + 192];
        g_invd[b * 2048 + ic * 64 + tid] = 1.f / den;
    }
}

// ---------------------------------------------------------------------------
// K3: out = lrelu( (adj + exp(lrelu(s_i+s_j)) * invd_i) @ h )
// block tile: 64 (i) x 128 (o), K=2048 (j) in chunks of 32, double-buffered.
// K-permuted fragment layout: logical mma k-index c=8s+u lives at smem col
// jl = 8*(u&3) + 2*s + (u>>2) -> every thread's A/B fragment loads are float4.
// N-remap: mma instr nt covers output cols o == nt (mod 4) in the warp span.
// ---------------------------------------------------------------------------
struct SmemK3 {
    float A[2][64][36];     // coefficient tile (tf32 bit patterns), natural j cols
    float Bt[2][32][128];   // h tile, rows = j_local, 16B-chunk XOR swizzled
    float sdst[2048];
    float ssrc[64];
    float invd[64];
};

__device__ __forceinline__ void coeff_tile(SmemK3& sm, int buf, int j0,
                                           const float4* v, int tid) {
#pragma unroll
    for (int t = 0; t < 2; t++) {
        int e = tid + t * 256;
        int r = e >> 3, c4 = (e & 7) * 4;
        float si = sm.ssrc[r];
        float id = sm.invd[r];
        uint4 o;
        o.x = f2tf(fmaf(__expf(lrelu(si + sm.sdst[j0 + c4 + 0])), id, v[t].x));
        o.y = f2tf(fmaf(__expf(lrelu(si + sm.sdst[j0 + c4 + 1])), id, v[t].y));
        o.z = f2tf(fmaf(__expf(lrelu(si + sm.sdst[j0 + c4 + 2])), id, v[t].z));
        o.w = f2tf(fmaf(__expf(lrelu(si + sm.sdst[j0 + c4 + 3])), id, v[t].w));
        *(uint4*)&sm.A[buf][r][c4] = o;
    }
}

__global__ __launch_bounds__(256) void k3_main(const float* __restrict__ adj,
                                               float* __restrict__ out) {
    extern __shared__ char smraw[];
    SmemK3& sm = *(SmemK3*)smraw;
    int tid = threadIdx.x, lane = tid & 31, w = tid >> 5;
    int wm = w >> 2, wn = w & 3, g = lane >> 2, tg = lane & 3;
    int b = blockIdx.y;
    int i0 = blockIdx.x * 64;
    const float* adjb = adj + ((long)b * 2048 + i0) * 2048;
    const float* hb = g_h + (long)b * 2048 * 128;

    // preload per-row vectors
#pragma unroll
    for (int t = 0; t < 2; t++) {
        int f = tid + t * 256;
        *(float4*)&sm.sdst[f * 4] = *(const float4*)(g_sdst + b * 2048 + f * 4);
    }
    if (tid < 64) {
        sm.ssrc[tid] = g_ssrc[b * 2048 + i0 + tid];
        sm.invd[tid] = g_invd[b * 2048 + i0 + tid];
    }

    float acc[2][4][4];
#pragma unroll
    for (int mt = 0; mt < 2; mt++)
#pragma unroll
        for (int nt = 0; nt < 4; nt++)
#pragma unroll
            for (int q = 0; q < 4; q++) acc[mt][nt][q] = 0.f;

    float4 v[2];
    const int bcol = (8 * wn + (g ^ (tg << 1))) * 4;   // swizzled B chunk col

    // chunk 0 prologue: B tile via cp.async (chunk-swizzled dst), adj into regs
#pragma unroll
    for (int t = 0; t < 4; t++) {
        int f = tid + t * 256;
        int r = f >> 5, cc = f & 31;
        int pc = cc ^ ((r >> 3) << 1);
        cp16(&sm.Bt[0][r][pc * 4], hb + (long)r * 128 + cc * 4);
    }
    cp_commit();
#pragma unroll
    for (int t = 0; t < 2; t++) {
        int e = tid + t * 256;
        int r = e >> 3, c4 = (e & 7) * 4;
        v[t] = __ldcs((const float4*)(adjb + (long)r * 2048 + c4));
    }
    __syncthreads();   // sdst/ssrc/invd visible
    coeff_tile(sm, 0, 0, v, tid);
    cp_wait0();
    __syncthreads();

    for (int c = 0; c < 64; c++) {
        int buf = c & 1;
        int j1 = (c + 1) * 32;
        if (c < 63) {
#pragma unroll
            for (int t = 0; t < 2; t++) {
                int e = tid + t * 256;
                int r = e >> 3, c4 = (e & 7) * 4;
                v[t] = __ldcs((const float4*)(adjb + (long)r * 2048 + j1 + c4));
            }
#pragma unroll
            for (int t = 0; t < 4; t++) {
                int f = tid + t * 256;
                int r = f >> 5, cc = f & 31;
                int pc = cc ^ ((r >> 3) << 1);
                cp16(&sm.Bt[buf ^ 1][r][pc * 4], hb + (long)(j1 + r) * 128 + cc * 4);
            }
            cp_commit();
        }

        // A fragments: per mt, rows rA and rA+8, 8 contiguous floats each
        float4 Afr[2][2][2];
#pragma unroll
        for (int mt = 0; mt < 2; mt++) {
            int rA = wm * 32 + mt * 16 + g;
            const float4* p0 = (const float4*)&sm.A[buf][rA][8 * tg];
            const float4* p1 = (const float4*)&sm.A[buf][rA + 8][8 * tg];
            Afr[mt][0][0] = p0[0]; Afr[mt][0][1] = p0[1];
            Afr[mt][1][0] = p1[0]; Afr[mt][1][1] = p1[1];
        }

#pragma unroll
        for (int s = 0; s < 4; s++) {
            float4 blo = *(const float4*)&sm.Bt[buf][8 * tg + 2 * s][bcol];
            float4 bhi = *(const float4*)&sm.Bt[buf][8 * tg + 2 * s + 1][bcol];
            const float* blof = (const float*)&blo;
            const float* bhif = (const float*)&bhi;
            int hs = s >> 1, off = (s & 1) * 2;
#pragma unroll
            for (int mt = 0; mt < 2; mt++) {
                const float* a0p = (const float*)&Afr[mt][0][hs];
                const float* a1p = (const float*)&Afr[mt][1][hs];
                uint32_t av[4];
                av[0] = __float_as_uint(a0p[off]);
                av[1] = __float_as_uint(a1p[off]);
                av[2] = __float_as_uint(a0p[off + 1]);
                av[3] = __float_as_uint(a1p[off + 1]);
#pragma unroll
                for (int nt = 0; nt < 4; nt++) {
                    uint32_t bv[2];
                    bv[0] = __float_as_uint(blof[nt]);
                    bv[1] = __float_as_uint(bhif[nt]);
                    mma8(acc[mt][nt], av, bv);
                }
            }
        }

        if (c < 63) {
            coeff_tile(sm, buf ^ 1, j1, v, tid);
            cp_wait0();
        }
        __syncthreads();
    }

    // epilogue: final leaky_relu; regather across nt -> float4 stores
    float* ob = out + ((long)b * 2048 + i0) * 128;
#pragma unroll
    for (int mt = 0; mt < 2; mt++)
#pragma unroll
        for (int half = 0; half < 2; half++) {
            int r = wm * 32 + mt * 16 + g + 8 * half;
            float4 v0, v1;
            v0.x = lrelu(acc[mt][0][2 * half]);
            v0.y = lrelu(acc[mt][1][2 * half]);
            v0.z = lrelu(acc[mt][2][2 * half]);
            v0.w = lrelu(acc[mt][3][2 * half]);
            v1.x = lrelu(acc[mt][0][2 * half + 1]);
            v1.y = lrelu(acc[mt][1][2 * half + 1]);
            v1.z = lrelu(acc[mt][2][2 * half + 1]);
            v1.w = lrelu(acc[mt][3][2 * half + 1]);
            *(float4*)(ob + (long)r * 128 + wn * 32 + 8 * tg) = v0;
            *(float4*)(ob + (long)r * 128 + wn * 32 + 8 * tg + 4) = v1;
        }
}

// ---------------------------------------------------------------------------
extern "C" void kernel_launch(void* const* d_in, const int* in_sizes, int n_in,
                              void* d_out, int out_size) {
    (void)in_sizes; (void)n_in; (void)out_size;
    const float* x   = (const float*)d_in[0];
    const float* adj = (const float*)d_in[1];
    const float* W   = (const float*)d_in[2];
    const float* a   = (const float*)d_in[3];
    float* out = (float*)d_out;

    k1_h<<<256, 256>>>(x, W, a);
    k2_den<<<256, 256>>>();
    cudaFuncSetAttribute(k3_main, cudaFuncAttributeMaxDynamicSharedMemorySize,
                         (int)sizeof(SmemK3));
    k3_main<<<dim3(32, 8), 256, sizeof(SmemK3)>>>(adj, out);
}

// round 3
// speedup vs baseline: 1.0877x; 1.0877x over previous
#include <cuda_runtime.h>
#include <cstdint>

#define NEG_SLOPE 0.2f

static constexpr int Bb = 8;
static constexpr int Nn = 2048;
static constexpr int Dd = 128;

// Scratch (device globals; allocation-free rule)
__device__ float g_h[Bb * Nn * Dd];      // h, rounded to tf32 values stored as fp32
__device__ float g_e1s[Bb * Nn];         // exp(s_src)
__device__ float g_e2s[Bb * Nn];         // exp(0.2*s_src)
__device__ float g_e1d[Bb * Nn];         // exp(s_dst)
__device__ float g_e2d[Bb * Nn];         // exp(0.2*s_dst)
__device__ float g_thr[Bb * Nn];         // exp(-s_src)  (cond: e1d_j > thr_i)
__device__ float g_invd[Bb * Nn];

__device__ __forceinline__ uint32_t f2tf(float x) {
    uint32_t r;
    asm("cvt.rna.tf32.f32 %0, %1;" : "=r"(r) : "f"(x));
    return r;
}

__device__ __forceinline__ float lrelu(float v) { return v > 0.f ? v : NEG_SLOPE * v; }

__device__ __forceinline__ void mma8(float* d, const uint32_t* a, const uint32_t* b) {
    asm volatile(
        "mma.sync.aligned.m16n8k8.row.col.f32.tf32.tf32.f32 "
        "{%0,%1,%2,%3},{%4,%5,%6,%7},{%8,%9},{%0,%1,%2,%3};\n"
        : "+f"(d[0]), "+f"(d[1]), "+f"(d[2]), "+f"(d[3])
        : "r"(a[0]), "r"(a[1]), "r"(a[2]), "r"(a[3]), "r"(b[0]), "r"(b[1]));
}

__device__ __forceinline__ void cp16(void* s, const void* g) {
    uint32_t sa = (uint32_t)__cvta_generic_to_shared(s);
    asm volatile("cp.async.cg.shared.global [%0], [%1], 16;" :: "r"(sa), "l"(g));
}
__device__ __forceinline__ void cp_commit() { asm volatile("cp.async.commit_group;"); }
__device__ __forceinline__ void cp_wait1()  { asm volatile("cp.async.wait_group 1;"); }

// ---------------------------------------------------------------------------
// K1: h = x @ W  (M=16384, N=128, K=128), tf32 mma, store tf32-rounded h.
// Epilogue computes s_src/s_dst per row and stores the exp-factor tables.
// ---------------------------------------------------------------------------
__global__ __launch_bounds__(256) void k1_h(const float* __restrict__ x,
                                            const float* __restrict__ W,
                                            const float* __restrict__ a) {
    __shared__ float As[64][36];
    __shared__ float Bs[32][136];
    __shared__ float red[64][2];
    int tid = threadIdx.x;
    int lane = tid & 31, w = tid >> 5;
    int wm = w >> 2, wn = w & 3;
    int g = lane >> 2, tg = lane & 3;
    long i0 = (long)blockIdx.x * 64;

    float2 asv[4], adv[4];
#pragma unroll
    for (int nt = 0; nt < 4; nt++) {
        int c = wn * 32 + nt * 8 + 2 * tg;
        asv[nt].x = __ldg(a + c);       asv[nt].y = __ldg(a + c + 1);
        adv[nt].x = __ldg(a + 128 + c); adv[nt].y = __ldg(a + 128 + c + 1);
    }
    if (tid < 128) ((float*)red)[tid] = 0.f;

    float acc[2][4][4];
#pragma unroll
    for (int mt = 0; mt < 2; mt++)
#pragma unroll
        for (int nt = 0; nt < 4; nt++)
#pragma unroll
            for (int q = 0; q < 4; q++) acc[mt][nt][q] = 0.f;

#pragma unroll
    for (int kc = 0; kc < 4; kc++) {
        int k0 = kc * 32;
        __syncthreads();
#pragma unroll
        for (int t = 0; t < 2; t++) {
            int e = tid + t * 256;
            int r = e >> 3, c4 = (e & 7) * 4;
            float4 xv = *(const float4*)(x + (i0 + r) * 128 + k0 + c4);
            uint4 o;
            o.x = f2tf(xv.x); o.y = f2tf(xv.y); o.z = f2tf(xv.z); o.w = f2tf(xv.w);
            *(uint4*)&As[r][c4] = o;
        }
#pragma unroll
        for (int t = 0; t < 4; t++) {
            int f = tid + t * 256;
            int r = f >> 5, c4 = (f & 31) * 4;
            float4 wv = *(const float4*)(W + (k0 + r) * 128 + c4);
            uint4 o;
            o.x = f2tf(wv.x); o.y = f2tf(wv.y); o.z = f2tf(wv.z); o.w = f2tf(wv.w);
            *(uint4*)&Bs[r][c4] = o;
        }
        __syncthreads();
#pragma unroll
        for (int ks = 0; ks < 4; ks++) {
            int ka = ks * 8;
            uint32_t af[2][4], bf[4][2];
#pragma unroll
            for (int mt = 0; mt < 2; mt++) {
                int rA = wm * 32 + mt * 16 + g;
                af[mt][0] = __float_as_uint(As[rA][ka + tg]);
                af[mt][1] = __float_as_uint(As[rA + 8][ka + tg]);
                af[mt][2] = __float_as_uint(As[rA][ka + tg + 4]);
                af[mt][3] = __float_as_uint(As[rA + 8][ka + tg + 4]);
            }
#pragma unroll
            for (int nt = 0; nt < 4; nt++) {
                int cB = wn * 32 + nt * 8 + g;
                bf[nt][0] = __float_as_uint(Bs[ka + tg][cB]);
                bf[nt][1] = __float_as_uint(Bs[ka + tg + 4][cB]);
            }
#pragma unroll
            for (int mt = 0; mt < 2; mt++)
#pragma unroll
                for (int nt = 0; nt < 4; nt++) mma8(acc[mt][nt], af[mt], bf[nt]);
        }
    }

#pragma unroll
    for (int mt = 0; mt < 2; mt++)
#pragma unroll
        for (int nt = 0; nt < 4; nt++) {
            long r = i0 + wm * 32 + mt * 16 + g;
            int c = wn * 32 + nt * 8 + 2 * tg;
            float2 v0, v1;
            v0.x = __uint_as_float(f2tf(acc[mt][nt][0]));
            v0.y = __uint_as_float(f2tf(acc[mt][nt][1]));
            v1.x = __uint_as_float(f2tf(acc[mt][nt][2]));
            v1.y = __uint_as_float(f2tf(acc[mt][nt][3]));
            *(float2*)(g_h + r * 128 + c) = v0;
            *(float2*)(g_h + (r + 8) * 128 + c) = v1;
        }

    // s_src/s_dst via shfl + smem-atomic reduction, then exp tables
    __syncthreads();
#pragma unroll
    for (int mt = 0; mt < 2; mt++)
#pragma unroll
        for (int half = 0; half < 2; half++) {
            int rl = wm * 32 + mt * 16 + g + 8 * half;
            float s = 0.f, d = 0.f;
#pragma unroll
            for (int nt = 0; nt < 4; nt++) {
                float v0 = acc[mt][nt][2 * half];
                float v1 = acc[mt][nt][2 * half + 1];
                s += v0 * asv[nt].x + v1 * asv[nt].y;
                d += v0 * adv[nt].x + v1 * adv[nt].y;
            }
            s += __shfl_xor_sync(0xFFFFFFFFu, s, 1);
            s += __shfl_xor_sync(0xFFFFFFFFu, s, 2);
            d += __shfl_xor_sync(0xFFFFFFFFu, d, 1);
            d += __shfl_xor_sync(0xFFFFFFFFu, d, 2);
            if (tg == 0) {
                atomicAdd(&red[rl][0], s);
                atomicAdd(&red[rl][1], d);
            }
        }
    __syncthreads();
    if (tid < 64) {
        float s = red[tid][0], d = red[tid][1];
        g_e1s[i0 + tid] = __expf(s);
        g_e2s[i0 + tid] = __expf(NEG_SLOPE * s);
        g_thr[i0 + tid] = __expf(-s);
        g_e1d[i0 + tid] = __expf(d);
        g_e2d[i0 + tid] = __expf(NEG_SLOPE * d);
    }
}

// ---------------------------------------------------------------------------
// K2: invd[i] = 1 / (e1s_i * sum_{e1d_j>thr_i} e1d_j + e2s_i * sum_else e2d_j)
// ---------------------------------------------------------------------------
__global__ __launch_bounds__(256) void k2_den() {
    __shared__ float sd1[2048];
    __shared__ float sd2[2048];
    __shared__ float2 part[256];
    int tid = threadIdx.x;
    int b = blockIdx.x >> 5, ic = blockIdx.x & 31;
#pragma unroll
    for (int t = 0; t < 2; t++) {
        int f = tid + t * 256;
        *(float4*)&sd1[f * 4] = *(const float4*)(g_e1d + b * 2048 + f * 4);
        *(float4*)&sd2[f * 4] = *(const float4*)(g_e2d + b * 2048 + f * 4);
    }
    int r = tid & 63, q = tid >> 6;
    int row = b * 2048 + ic * 64 + r;
    float thr = g_thr[row];
    __syncthreads();
    float a1 = 0.f, a2 = 0.f;
    int j0 = q * 512;
#pragma unroll 8
    for (int j = 0; j < 512; j++) {
        float v1 = sd1[j0 + j];
        float v2 = sd2[j0 + j];
        bool c = v1 > thr;
        a1 += c ? v1 : 0.f;
        a2 += c ? 0.f : v2;
    }
    part[tid] = make_float2(a1, a2);
    __syncthreads();
    if (tid < 64) {
        float2 p0 = part[tid], p1 = part[tid + 64], p2 = part[tid + 128], p3 = part[tid + 192];
        float A1 = p0.x + p1.x + p2.x + p3.x;
        float A2 = p0.y + p1.y + p2.y + p3.y;
        float den = g_e1s[row] * A1 + g_e2s[row] * A2;
        g_invd[row] = 1.f / den;
    }
}

// ---------------------------------------------------------------------------
// K3: out = lrelu( (adj + softmax-term) @ h )
// coeff_ij = adj_ij + (e1d_j > thr_i ? p1_i*e1d_j : p2_i*e2d_j),
//   p1_i = e1s_i*invd_i, p2_i = e2s_i*invd_i.   No MUFU in the mainloop.
// adj: 4-stage cp.async ring (distance-4 issue). Bt(h): 2-stage cp.async.
// ---------------------------------------------------------------------------
struct SmemK3 {
    float A[2][64][36];       // coefficient tile (tf32 bit patterns)
    float Bt[2][32][128];     // h tile, 16B-chunk XOR swizzled
    float adjS[4][64][32];    // adj staging ring
    float e1d[2048];
    float e2d[2048];
};

__global__ __launch_bounds__(256) void k3_main(const float* __restrict__ adj,
                                               float* __restrict__ out) {
    extern __shared__ char smraw[];
    SmemK3& sm = *(SmemK3*)smraw;
    int tid = threadIdx.x, lane = tid & 31, w = tid >> 5;
    int wm = w >> 2, wn = w & 3, g = lane >> 2, tg = lane & 3;
    int b = blockIdx.y;
    int i0 = blockIdx.x * 64;
    const float* adjb = adj + ((long)b * 2048 + i0) * 2048;
    const float* hb = g_h + (long)b * 2048 * 128;

    // preload e1d/e2d tables for this batch
#pragma unroll
    for (int t = 0; t < 2; t++) {
        int f = tid + t * 256;
        *(float4*)&sm.e1d[f * 4] = *(const float4*)(g_e1d + b * 2048 + f * 4);
        *(float4*)&sm.e2d[f * 4] = *(const float4*)(g_e2d + b * 2048 + f * 4);
    }
    // per-thread row params: this thread produces coeff rows (tid>>3) and (tid>>3)+32
    float p1r[2], p2r[2], thrr[2];
#pragma unroll
    for (int t = 0; t < 2; t++) {
        int r = (tid >> 3) + 32 * t;
        int base = b * 2048 + i0 + r;
        float iv = g_invd[base];
        p1r[t] = g_e1s[base] * iv;
        p2r[t] = g_e2s[base] * iv;
        thrr[t] = g_thr[base];
    }

    float acc[2][4][4];
#pragma unroll
    for (int mt = 0; mt < 2; mt++)
#pragma unroll
        for (int nt = 0; nt < 4; nt++)
#pragma unroll
            for (int q = 0; q < 4; q++) acc[mt][nt][q] = 0.f;

    const int bcol = (8 * wn + (g ^ (tg << 1))) * 4;   // swizzled B chunk col
    const int ar = tid >> 3, ac4 = (tid & 7) * 4;      // adj/coeff element coords

    // ---- prologue: commit {adj0,adj1,adj2,Bt0}, then {adj3}
#pragma unroll
    for (int s = 0; s < 3; s++) {
#pragma unroll
        for (int t = 0; t < 2; t++) {
            int r = ar + 32 * t;
            cp16(&sm.adjS[s][r][ac4], adjb + (long)r * 2048 + s * 32 + ac4);
        }
    }
#pragma unroll
    for (int t = 0; t < 4; t++) {
        int f = tid + t * 256;
        int r = f >> 5, cc = f & 31;
        int pc = cc ^ ((r >> 3) << 1);
        cp16(&sm.Bt[0][r][pc * 4], hb + (long)r * 128 + cc * 4);
    }
    cp_commit();
#pragma unroll
    for (int t = 0; t < 2; t++) {
        int r = ar + 32 * t;
        cp16(&sm.adjS[3][r][ac4], adjb + (long)r * 2048 + 96 + ac4);
    }
    cp_commit();

    for (int c = 0; c < 64; c++) {
        int buf = c & 1, astage = c & 3;
        cp_wait1();
        __syncthreads();

        // coeff tile: adjS[astage] + exp-factor tables -> A[buf]
        int j0 = c * 32;
#pragma unroll
        for (int t = 0; t < 2; t++) {
            int r = ar + 32 * t;
            float4 av = *(const float4*)&sm.adjS[astage][r][ac4];
            float4 v1 = *(const float4*)&sm.e1d[j0 + ac4];
            float4 v2 = *(const float4*)&sm.e2d[j0 + ac4];
            float p1 = p1r[t], p2 = p2r[t], th = thrr[t];
            uint4 o;
            o.x = f2tf(fmaf(v1.x > th ? p1 : p2, v1.x > th ? v1.x : v2.x, av.x));
            o.y = f2tf(fmaf(v1.y > th ? p1 : p2, v1.y > th ? v1.y : v2.y, av.y));
            o.z = f2tf(fmaf(v1.z > th ? p1 : p2, v1.z > th ? v1.z : v2.z, av.z));
            o.w = f2tf(fmaf(v1.w > th ? p1 : p2, v1.w > th ? v1.w : v2.w, av.w));
            *(uint4*)&sm.A[buf][r][ac4] = o;
        }
        __syncthreads();

        // issue next-chunk loads: Bt(c+1) [group], adj(c+4) [group]
        {
            int cb = (c + 1 < 64) ? c + 1 : 63;
#pragma unroll
            for (int t = 0; t < 4; t++) {
                int f = tid + t * 256;
                int r = f >> 5, cc = f & 31;
                int pc = cc ^ ((r >> 3) << 1);
                cp16(&sm.Bt[buf ^ 1][r][pc * 4], hb + (long)(cb * 32 + r) * 128 + cc * 4);
            }
            cp_commit();
            int ca = (c + 4 < 64) ? c + 4 : 63;
#pragma unroll
            for (int t = 0; t < 2; t++) {
                int r = ar + 32 * t;
                cp16(&sm.adjS[(c + 4) & 3][r][ac4], adjb + (long)r * 2048 + ca * 32 + ac4);
            }
            cp_commit();
        }

        // A fragments: per mt, rows rA and rA+8, 8 contiguous floats each
        float4 Afr[2][2][2];
#pragma unroll
        for (int mt = 0; mt < 2; mt++) {
            int rA = wm * 32 + mt * 16 + g;
            const float4* p0 = (const float4*)&sm.A[buf][rA][8 * tg];
            const float4* p1 = (const float4*)&sm.A[buf][rA + 8][8 * tg];
            Afr[mt][0][0] = p0[0]; Afr[mt][0][1] = p0[1];
            Afr[mt][1][0] = p1[0]; Afr[mt][1][1] = p1[1];
        }

#pragma unroll
        for (int s = 0; s < 4; s++) {
            float4 blo = *(const float4*)&sm.Bt[buf][8 * tg + 2 * s][bcol];
            float4 bhi = *(const float4*)&sm.Bt[buf][8 * tg + 2 * s + 1][bcol];
            const float* blof = (const float*)&blo;
            const float* bhif = (const float*)&bhi;
            int hs = s >> 1, off = (s & 1) * 2;
#pragma unroll
            for (int mt = 0; mt < 2; mt++) {
                const float* a0p = (const float*)&Afr[mt][0][hs];
                const float* a1p = (const float*)&Afr[mt][1][hs];
                uint32_t av[4];
                av[0] = __float_as_uint(a0p[off]);
                av[1] = __float_as_uint(a1p[off]);
                av[2] = __float_as_uint(a0p[off + 1]);
                av[3] = __float_as_uint(a1p[off + 1]);
#pragma unroll
                for (int nt = 0; nt < 4; nt++) {
                    uint32_t bv[2];
                    bv[0] = __float_as_uint(blof[nt]);
                    bv[1] = __float_as_uint(bhif[nt]);
                    mma8(acc[mt][nt], av, bv);
                }
            }
        }
    }

    // epilogue: final leaky_relu; regather across nt -> float4 stores
    float* ob = out + ((long)b * 2048 + i0) * 128;
#pragma unroll
    for (int mt = 0; mt < 2; mt++)
#pragma unroll
        for (int half = 0; half < 2; half++) {
            int r = wm * 32 + mt * 16 + g + 8 * half;
            float4 v0, v1;
            v0.x = lrelu(acc[mt][0][2 * half]);
            v0.y = lrelu(acc[mt][1][2 * half]);
            v0.z = lrelu(acc[mt][2][2 * half]);
            v0.w = lrelu(acc[mt][3][2 * half]);
            v1.x = lrelu(acc[mt][0][2 * half + 1]);
            v1.y = lrelu(acc[mt][1][2 * half + 1]);
            v1.z = lrelu(acc[mt][2][2 * half + 1]);
            v1.w = lrelu(acc[mt][3][2 * half + 1]);
            *(float4*)(ob + (long)r * 128 + wn * 32 + 8 * tg) = v0;
            *(float4*)(ob + (long)r * 128 + wn * 32 + 8 * tg + 4) = v1;
        }
}

// ---------------------------------------------------------------------------
extern "C" void kernel_launch(void* const* d_in, const int* in_sizes, int n_in,
                              void* d_out, int out_size) {
    (void)in_sizes; (void)n_in; (void)out_size;
    const float* x   = (const float*)d_in[0];
    const float* adj = (const float*)d_in[1];
    const float* W   = (const float*)d_in[2];
    const float* a   = (const float*)d_in[3];
    float* out = (float*)d_out;

    k1_h<<<256, 256>>>(x, W, a);
    k2_den<<<256, 256>>>();
    cudaFuncSetAttribute(k3_main, cudaFuncAttributeMaxDynamicSharedMemorySize,
                         (int)sizeof(SmemK3));
    k3_main<<<dim3(32, 8), 256, sizeof(SmemK3)>>>(adj, out);
}

// round 5
// speedup vs baseline: 1.2400x; 1.1400x over previous
#include <cuda_runtime.h>
#include <cstdint>

#define NEG_SLOPE 0.2f

static constexpr int Bb = 8;
static constexpr int Nn = 2048;
static constexpr int Dd = 128;

// Scratch (device globals; allocation-free rule)
__device__ float g_h[Bb * Nn * Dd];      // h, tf32-rounded, natural [b][j][o]
__device__ float g_e1s[Bb * Nn];         // exp(s_src)
__device__ float g_e2s[Bb * Nn];         // exp(0.2*s_src)
__device__ float g_e1d[Bb * Nn];         // exp(s_dst)
__device__ float g_e2d[Bb * Nn];         // exp(0.2*s_dst)
__device__ float g_thr[Bb * Nn];         // exp(-s_src)  (cond: e1d_j > thr_i)
__device__ float g_invd[Bb * Nn];

__device__ __forceinline__ uint32_t f2tf(float x) {
    uint32_t r;
    asm("cvt.rna.tf32.f32 %0, %1;" : "=r"(r) : "f"(x));
    return r;
}
__device__ __forceinline__ float lrelu(float v) { return v > 0.f ? v : NEG_SLOPE * v; }

__device__ __forceinline__ void mma8(float* d, const uint32_t* a, const uint32_t* b) {
    asm volatile(
        "mma.sync.aligned.m16n8k8.row.col.f32.tf32.tf32.f32 "
        "{%0,%1,%2,%3},{%4,%5,%6,%7},{%8,%9},{%0,%1,%2,%3};\n"
        : "+f"(d[0]), "+f"(d[1]), "+f"(d[2]), "+f"(d[3])
        : "r"(a[0]), "r"(a[1]), "r"(a[2]), "r"(a[3]), "r"(b[0]), "r"(b[1]));
}

__device__ __forceinline__ void cp16(void* s, const void* g) {
    uint32_t sa = (uint32_t)__cvta_generic_to_shared(s);
    asm volatile("cp.async.cg.shared.global [%0], [%1], 16;" :: "r"(sa), "l"(g));
}
__device__ __forceinline__ void cp_commit() { asm volatile("cp.async.commit_group;"); }

__device__ __forceinline__ void bar_sync(int id, int cnt) {
    asm volatile("bar.sync %0, %1;" :: "r"(id), "r"(cnt) : "memory");
}
__device__ __forceinline__ void bar_arrive(int id, int cnt) {
    asm volatile("bar.arrive %0, %1;" :: "r"(id), "r"(cnt) : "memory");
}

// ---------------------------------------------------------------------------
// K1: h = x @ W  (M=16384, N=128, K=128), tf32 mma.sync; epilogue computes
// s_src/s_dst per row and stores the exp-factor tables.
// ---------------------------------------------------------------------------
__global__ __launch_bounds__(256) void k1_h(const float* __restrict__ x,
                                            const float* __restrict__ W,
                                            const float* __restrict__ a) {
    __shared__ float As[64][36];
    __shared__ float Bs[32][136];
    __shared__ float red[64][2];
    int tid = threadIdx.x;
    int lane = tid & 31, w = tid >> 5;
    int wm = w >> 2, wn = w & 3;
    int g = lane >> 2, tg = lane & 3;
    long i0 = (long)blockIdx.x * 64;

    float2 asv[4], adv[4];
#pragma unroll
    for (int nt = 0; nt < 4; nt++) {
        int c = wn * 32 + nt * 8 + 2 * tg;
        asv[nt].x = __ldg(a + c);       asv[nt].y = __ldg(a + c + 1);
        adv[nt].x = __ldg(a + 128 + c); adv[nt].y = __ldg(a + 128 + c + 1);
    }
    if (tid < 128) ((float*)red)[tid] = 0.f;

    float acc[2][4][4];
#pragma unroll
    for (int mt = 0; mt < 2; mt++)
#pragma unroll
        for (int nt = 0; nt < 4; nt++)
#pragma unroll
            for (int q = 0; q < 4; q++) acc[mt][nt][q] = 0.f;

#pragma unroll
    for (int kc = 0; kc < 4; kc++) {
        int k0 = kc * 32;
        __syncthreads();
#pragma unroll
        for (int t = 0; t < 2; t++) {
            int e = tid + t * 256;
            int r = e >> 3, c4 = (e & 7) * 4;
            float4 xv = *(const float4*)(x + (i0 + r) * 128 + k0 + c4);
            uint4 o;
            o.x = f2tf(xv.x); o.y = f2tf(xv.y); o.z = f2tf(xv.z); o.w = f2tf(xv.w);
            *(uint4*)&As[r][c4] = o;
        }
#pragma unroll
        for (int t = 0; t < 4; t++) {
            int f = tid + t * 256;
            int r = f >> 5, c4 = (f & 31) * 4;
            float4 wv = *(const float4*)(W + (k0 + r) * 128 + c4);
            uint4 o;
            o.x = f2tf(wv.x); o.y = f2tf(wv.y); o.z = f2tf(wv.z); o.w = f2tf(wv.w);
            *(uint4*)&Bs[r][c4] = o;
        }
        __syncthreads();
#pragma unroll
        for (int ks = 0; ks < 4; ks++) {
            int ka = ks * 8;
            uint32_t af[2][4], bf[4][2];
#pragma unroll
            for (int mt = 0; mt < 2; mt++) {
                int rA = wm * 32 + mt * 16 + g;
                af[mt][0] = __float_as_uint(As[rA][ka + tg]);
                af[mt][1] = __float_as_uint(As[rA + 8][ka + tg]);
                af[mt][2] = __float_as_uint(As[rA][ka + tg + 4]);
                af[mt][3] = __float_as_uint(As[rA + 8][ka + tg + 4]);
            }
#pragma unroll
            for (int nt = 0; nt < 4; nt++) {
                int cB = wn * 32 + nt * 8 + g;
                bf[nt][0] = __float_as_uint(Bs[ka + tg][cB]);
                bf[nt][1] = __float_as_uint(Bs[ka + tg + 4][cB]);
            }
#pragma unroll
            for (int mt = 0; mt < 2; mt++)
#pragma unroll
                for (int nt = 0; nt < 4; nt++) mma8(acc[mt][nt], af[mt], bf[nt]);
        }
    }

#pragma unroll
    for (int mt = 0; mt < 2; mt++)
#pragma unroll
        for (int nt = 0; nt < 4; nt++) {
            long r = i0 + wm * 32 + mt * 16 + g;
            int c = wn * 32 + nt * 8 + 2 * tg;
            float2 v0, v1;
            v0.x = __uint_as_float(f2tf(acc[mt][nt][0]));
            v0.y = __uint_as_float(f2tf(acc[mt][nt][1]));
            v1.x = __uint_as_float(f2tf(acc[mt][nt][2]));
            v1.y = __uint_as_float(f2tf(acc[mt][nt][3]));
            *(float2*)(g_h + r * 128 + c) = v0;
            *(float2*)(g_h + (r + 8) * 128 + c) = v1;
        }

    // s_src/s_dst via shfl + smem-atomic reduction, then exp tables
    __syncthreads();
#pragma unroll
    for (int mt = 0; mt < 2; mt++)
#pragma unroll
        for (int half = 0; half < 2; half++) {
            int rl = wm * 32 + mt * 16 + g + 8 * half;
            float s = 0.f, d = 0.f;
#pragma unroll
            for (int nt = 0; nt < 4; nt++) {
                float v0 = acc[mt][nt][2 * half];
                float v1 = acc[mt][nt][2 * half + 1];
                s += v0 * asv[nt].x + v1 * asv[nt].y;
                d += v0 * adv[nt].x + v1 * adv[nt].y;
            }
            s += __shfl_xor_sync(0xFFFFFFFFu, s, 1);
            s += __shfl_xor_sync(0xFFFFFFFFu, s, 2);
            d += __shfl_xor_sync(0xFFFFFFFFu, d, 1);
            d += __shfl_xor_sync(0xFFFFFFFFu, d, 2);
            if (tg == 0) {
                atomicAdd(&red[rl][0], s);
                atomicAdd(&red[rl][1], d);
            }
        }
    __syncthreads();
    if (tid < 64) {
        float s = red[tid][0], d = red[tid][1];
        g_e1s[i0 + tid] = __expf(s);
        g_e2s[i0 + tid] = __expf(NEG_SLOPE * s);
        g_thr[i0 + tid] = __expf(-s);
        g_e1d[i0 + tid] = __expf(d);
        g_e2d[i0 + tid] = __expf(NEG_SLOPE * d);
    }
}

// ---------------------------------------------------------------------------
// K2: invd[i] = 1 / (e1s_i * sum_{e1d_j>thr_i} e1d_j + e2s_i * sum_else e2d_j)
// ---------------------------------------------------------------------------
__global__ __launch_bounds__(256) void k2_den() {
    __shared__ float sd1[2048];
    __shared__ float sd2[2048];
    __shared__ float2 part[256];
    int tid = threadIdx.x;
    int b = blockIdx.x >> 5, ic = blockIdx.x & 31;
#pragma unroll
    for (int t = 0; t < 2; t++) {
        int f = tid + t * 256;
        *(float4*)&sd1[f * 4] = *(const float4*)(g_e1d + b * 2048 + f * 4);
        *(float4*)&sd2[f * 4] = *(const float4*)(g_e2d + b * 2048 + f * 4);
    }
    int r = tid & 63, q = tid >> 6;
    int row = b * 2048 + ic * 64 + r;
    float thr = g_thr[row];
    __syncthreads();
    float a1 = 0.f, a2 = 0.f;
    int j0 = q * 512;
#pragma unroll 8
    for (int j = 0; j < 512; j++) {
        float v1 = sd1[j0 + j];
        float v2 = sd2[j0 + j];
        bool c = v1 > thr;
        a1 += c ? v1 : 0.f;
        a2 += c ? 0.f : v2;
    }
    part[tid] = make_float2(a1, a2);
    __syncthreads();
    if (tid < 64) {
        float2 p0 = part[tid], p1 = part[tid + 64], p2 = part[tid + 128], p3 = part[tid + 192];
        float den = g_e1s[row] * (p0.x + p1.x + p2.x + p3.x) +
                    g_e2s[row] * (p0.y + p1.y + p2.y + p3.y);
        g_invd[row] = 1.f / den;
    }
}

// ---------------------------------------------------------------------------
// K3: out = lrelu( (adj + softmax-term) @ h ), warp-specialized.
// 384 threads: warps 0-7 consume (mma.sync, 128x128 block, 32x64 warp tile),
// warps 8-11 produce (adj LDG + coeff transform -> A ring; h via cp.async -> B ring).
// 4-stage rings; named barriers: full[s]=1+s, free[s]=5+s (count 384).
// ---------------------------------------------------------------------------
struct SmemK3 {
    float A[4][128][36];      // coeff tiles (tf32 bits), natural j cols, padded
    float Bt[4][32][128];     // h tiles, rows=j_local, 16B-chunk XOR swizzled
    float e1[2048];
    float e2[2048];
};

__global__ __launch_bounds__(384) void k3_main(const float* __restrict__ adj,
                                               float* __restrict__ out) {
    extern __shared__ char smraw[];
    SmemK3& sm = *(SmemK3*)smraw;
    int tid = threadIdx.x, lane = tid & 31, w = tid >> 5;
    int b = blockIdx.y;
    int i0 = blockIdx.x * 128;
    const float* adjb = adj + ((long)b * 2048 + i0) * 2048;
    const float* hb = g_h + (long)b * 2048 * 128;

    // all threads: load e1d/e2d tables, then one full sync
    for (int f = tid; f < 512; f += 384) {
        *(float4*)&sm.e1[f * 4] = *(const float4*)(g_e1d + b * 2048 + f * 4);
        *(float4*)&sm.e2[f * 4] = *(const float4*)(g_e2d + b * 2048 + f * 4);
    }
    __syncthreads();

    if (w >= 8) {
        // ================= PRODUCERS (warps 8-11, 128 threads) =============
        int ptid = tid - 256;
        int pr = ptid >> 3, pc8 = ptid & 7;   // rows pr+16t, col chunk pc8
        float p1r[8], p2r[8], thrr[8];
#pragma unroll
        for (int t = 0; t < 8; t++) {
            int gr = b * 2048 + i0 + pr + 16 * t;
            float iv = g_invd[gr];
            p1r[t] = g_e1s[gr] * iv;
            p2r[t] = g_e2s[gr] * iv;
            thrr[t] = g_thr[gr];
        }
        float4 adjR[2][8];
#pragma unroll
        for (int t = 0; t < 8; t++)
            adjR[0][t] = __ldcs((const float4*)(adjb + (long)(pr + 16 * t) * 2048 + pc8 * 4));
        // prologue: issue B[0]
#pragma unroll
        for (int k = 0; k < 8; k++) {
            int f = ptid + k * 128;
            int r = f >> 5, cc = f & 31;
            int pc = cc ^ ((r >> 3) << 1);
            cp16(&sm.Bt[0][r][pc * 4], hb + (long)r * 128 + cc * 4);
        }
        cp_commit();

#pragma unroll 2
        for (int c = 0; c < 64; c++) {
            int s = c & 3;
            // stage for B[c+1]: wait it free, then issue
            if (c + 1 < 64) {
                if (c + 1 >= 4) bar_sync(5 + ((c + 1) & 3), 384);
#pragma unroll
                for (int k = 0; k < 8; k++) {
                    int f = ptid + k * 128;
                    int r = f >> 5, cc = f & 31;
                    int pc = cc ^ ((r >> 3) << 1);
                    cp16(&sm.Bt[(c + 1) & 3][r][pc * 4],
                         hb + (long)((c + 1) * 32 + r) * 128 + cc * 4);
                }
                cp_commit();
            }
            // coeff tile chunk c -> A[s]  (stage s freed by the wait at iter c-1)
            float4 v1 = *(const float4*)&sm.e1[c * 32 + pc8 * 4];
            float4 v2 = *(const float4*)&sm.e2[c * 32 + pc8 * 4];
#pragma unroll
            for (int t = 0; t < 8; t++) {
                float4 av = adjR[c & 1][t];
                float p1 = p1r[t], p2 = p2r[t], th = thrr[t];
                uint4 o;
                o.x = f2tf(fmaf(v1.x > th ? p1 : p2, v1.x > th ? v1.x : v2.x, av.x));
                o.y = f2tf(fmaf(v1.y > th ? p1 : p2, v1.y > th ? v1.y : v2.y, av.y));
                o.z = f2tf(fmaf(v1.z > th ? p1 : p2, v1.z > th ? v1.z : v2.z, av.z));
                o.w = f2tf(fmaf(v1.w > th ? p1 : p2, v1.w > th ? v1.w : v2.w, av.w));
                *(uint4*)&sm.A[s][pr + 16 * t][pc8 * 4] = o;
            }
            // adj prefetch chunk c+1
            if (c + 1 < 64) {
#pragma unroll
                for (int t = 0; t < 8; t++)
                    adjR[(c + 1) & 1][t] =
                        __ldcs((const float4*)(adjb + (long)(pr + 16 * t) * 2048 +
                                               (c + 1) * 32 + pc8 * 4));
            }
            // B[c] landed?  (B[c+1] may remain in flight)
            if (c + 1 < 64)
                asm volatile("cp.async.wait_group 1;" ::: "memory");
            else
                asm volatile("cp.async.wait_group 0;" ::: "memory");
            bar_arrive(1 + s, 384);
        }
    } else {
        // ================= CONSUMERS (warps 0-7, 256 threads) ==============
        int wr = w & 3, wc = w >> 2;          // rows wr*32.., cols wc*64..
        int g = lane >> 2, tg = lane & 3;
        float acc[2][2][4][4];
#pragma unroll
        for (int mt = 0; mt < 2; mt++)
#pragma unroll
            for (int sp = 0; sp < 2; sp++)
#pragma unroll
                for (int nt = 0; nt < 4; nt++)
#pragma unroll
                    for (int q = 0; q < 4; q++) acc[mt][sp][nt][q] = 0.f;

        int bcol0 = ((wc * 2 + 0) * 8 + (g ^ (tg << 1))) * 4;
        int bcol1 = ((wc * 2 + 1) * 8 + (g ^ (tg << 1))) * 4;

        for (int c = 0; c < 64; c++) {
            int s = c & 3;
            bar_sync(1 + s, 384);

            float4 Afr[2][2][2];
#pragma unroll
            for (int mt = 0; mt < 2; mt++) {
                int rA = wr * 32 + mt * 16 + g;
                const float4* p0 = (const float4*)&sm.A[s][rA][8 * tg];
                const float4* p1 = (const float4*)&sm.A[s][rA + 8][8 * tg];
                Afr[mt][0][0] = p0[0]; Afr[mt][0][1] = p0[1];
                Afr[mt][1][0] = p1[0]; Afr[mt][1][1] = p1[1];
            }
#pragma unroll
            for (int ss = 0; ss < 4; ss++) {
                int hs = ss >> 1, off = (ss & 1) * 2;
                uint32_t av[2][4];
#pragma unroll
                for (int mt = 0; mt < 2; mt++) {
                    const float* a0p = (const float*)&Afr[mt][0][hs];
                    const float* a1p = (const float*)&Afr[mt][1][hs];
                    av[mt][0] = __float_as_uint(a0p[off]);
                    av[mt][1] = __float_as_uint(a1p[off]);
                    av[mt][2] = __float_as_uint(a0p[off + 1]);
                    av[mt][3] = __float_as_uint(a1p[off + 1]);
                }
#pragma unroll
                for (int sp = 0; sp < 2; sp++) {
                    int bc = sp ? bcol1 : bcol0;
                    float4 blo = *(const float4*)&sm.Bt[s][8 * tg + 2 * ss][bc];
                    float4 bhi = *(const float4*)&sm.Bt[s][8 * tg + 2 * ss + 1][bc];
                    const float* blof = (const float*)&blo;
                    const float* bhif = (const float*)&bhi;
#pragma unroll
                    for (int mt = 0; mt < 2; mt++)
#pragma unroll
                        for (int nt = 0; nt < 4; nt++) {
                            uint32_t bv[2];
                            bv[0] = __float_as_uint(blof[nt]);
                            bv[1] = __float_as_uint(bhif[nt]);
                            mma8(acc[mt][sp][nt], av[mt], bv);
                        }
                }
            }
            bar_arrive(5 + s, 384);
        }

        // epilogue: lrelu + regather across nt -> float4 stores
        float* ob = out + ((long)b * 2048 + i0) * 128;
#pragma unroll
        for (int mt = 0; mt < 2; mt++)
#pragma unroll
            for (int half = 0; half < 2; half++) {
                int r = wr * 32 + mt * 16 + g + 8 * half;
#pragma unroll
                for (int sp = 0; sp < 2; sp++) {
                    float4 v0, v1;
                    v0.x = lrelu(acc[mt][sp][0][2 * half]);
                    v0.y = lrelu(acc[mt][sp][1][2 * half]);
                    v0.z = lrelu(acc[mt][sp][2][2 * half]);
                    v0.w = lrelu(acc[mt][sp][3][2 * half]);
                    v1.x = lrelu(acc[mt][sp][0][2 * half + 1]);
                    v1.y = lrelu(acc[mt][sp][1][2 * half + 1]);
                    v1.z = lrelu(acc[mt][sp][2][2 * half + 1]);
                    v1.w = lrelu(acc[mt][sp][3][2 * half + 1]);
                    int cb = wc * 64 + sp * 32 + 8 * tg;
                    *(float4*)(ob + (long)r * 128 + cb) = v0;
                    *(float4*)(ob + (long)r * 128 + cb + 4) = v1;
                }
            }
    }
}

// ---------------------------------------------------------------------------
extern "C" void kernel_launch(void* const* d_in, const int* in_sizes, int n_in,
                              void* d_out, int out_size) {
    (void)in_sizes; (void)n_in; (void)out_size;
    const float* x   = (const float*)d_in[0];
    const float* adj = (const float*)d_in[1];
    const float* W   = (const float*)d_in[2];
    const float* a   = (const float*)d_in[3];
    float* out = (float*)d_out;

    k1_h<<<256, 256>>>(x, W, a);
    k2_den<<<256, 256>>>();
    cudaFuncSetAttribute(k3_main, cudaFuncAttributeMaxDynamicSharedMemorySize,
                         (int)sizeof(SmemK3));
    k3_main<<<dim3(16, 8), 384, sizeof(SmemK3)>>>(adj, out);
}